// round 12
// baseline (speedup 1.0000x reference)
#include <cuda_runtime.h>
#include <cuda_fp16.h>
#include <cstdint>

#define BATCH 16
#define CIN   256
#define MED   128
#define NPIX  4096

// ---------------- scratch ----------------
__device__ __half g_Wh[256 * 256];                    // stacked [w_o; w_v] half
__device__ __half g_Wch[256 * 128];                   // w_c half [c][k]
__device__ float  g_bias[256];
__device__ __half g_oh[(size_t)BATCH * 128 * NPIX];   // o half
__device__ __half g_eh[(size_t)BATCH * 128 * NPIX];   // F = e^v * rsqrt(colsum) half
__device__ float  g_rowpart[BATCH * MED * 32];        // partial row sums of e^v
__device__ __half g_Aph[(size_t)BATCH * 8 * MED * MED]; // split-K partials of S (half)
__device__ __half g_Wbh[BATCH * 256 * MED];           // Wb half [b][c][m]

// ======================= helpers =======================
__device__ __forceinline__ uint32_t smem_u32(const void* p) {
    uint32_t a;
    asm("{ .reg .u64 t; cvta.to.shared.u64 t, %1; cvt.u32.u64 %0, t; }" : "=r"(a) : "l"(p));
    return a;
}

#define CP16(dst, src) \
    asm volatile("cp.async.ca.shared.global [%0], [%1], 16;" :: "r"(dst), "l"(src) : "memory")
#define CP_COMMIT asm volatile("cp.async.commit_group;" ::: "memory")
#define CP_WAIT1  asm volatile("cp.async.wait_group 1;" ::: "memory")
#define CP_WAIT0  asm volatile("cp.async.wait_group 0;" ::: "memory")

__device__ __forceinline__ void mma_f16(float* d, const uint32_t* a, const uint32_t* b) {
    asm volatile(
        "mma.sync.aligned.m16n8k16.row.col.f32.f16.f16.f32 "
        "{%0,%1,%2,%3}, {%4,%5,%6,%7}, {%8,%9}, {%0,%1,%2,%3};"
        : "+f"(d[0]), "+f"(d[1]), "+f"(d[2]), "+f"(d[3])
        : "r"(a[0]), "r"(a[1]), "r"(a[2]), "r"(a[3]), "r"(b[0]), "r"(b[1]));
}

__device__ __forceinline__ void ldsm_x4(uint32_t* r, uint32_t a) {
    asm volatile("ldmatrix.sync.aligned.m8n8.x4.shared.b16 {%0,%1,%2,%3}, [%4];"
                 : "=r"(r[0]), "=r"(r[1]), "=r"(r[2]), "=r"(r[3]) : "r"(a));
}
__device__ __forceinline__ void ldsm_x4_t(uint32_t* r, uint32_t a) {
    asm volatile("ldmatrix.sync.aligned.m8n8.x4.trans.shared.b16 {%0,%1,%2,%3}, [%4];"
                 : "=r"(r[0]), "=r"(r[1]), "=r"(r[2]), "=r"(r[3]) : "r"(a));
}

#define AH_STRIDE 40    // halfs; 80B rows
#define BH_STRIDE 136   // halfs; 272B rows

// ---- fp16 k-tile (K=32): A [m][k] stride 40, B raw [k][n] stride 136 ----
__device__ __forceinline__ void compute_tile_f16(uint32_t ahAddr, uint32_t bwAddr,
                                                 int lane, int wm, int wn, float acc[2][8][4]) {
#pragma unroll
    for (int ks = 0; ks < 2; ks++) {
        const int k0 = ks * 16;
        uint32_t a[2][4];
#pragma unroll
        for (int i = 0; i < 2; i++) {
            int row = wm + i * 16 + (lane & 15);
            int kof = k0 + ((lane >> 4) << 3);
            ldsm_x4(a[i], ahAddr + row * (AH_STRIDE * 2) + kof * 2);
        }
        uint32_t bb[8][2];
#pragma unroll
        for (int j16 = 0; j16 < 4; j16++) {
            int krow = k0 + (lane & 7) + ((lane & 8) ? 8 : 0);
            int ncol = wn + j16 * 16 + ((lane & 16) ? 8 : 0);
            uint32_t rr[4];
            ldsm_x4_t(rr, bwAddr + krow * (BH_STRIDE * 2) + ncol * 2);
            bb[j16 * 2][0] = rr[0]; bb[j16 * 2][1] = rr[1];
            bb[j16 * 2 + 1][0] = rr[2]; bb[j16 * 2 + 1][1] = rr[3];
        }
#pragma unroll
        for (int i = 0; i < 2; i++)
#pragma unroll
            for (int j = 0; j < 8; j++)
                mma_f16(acc[i][j], a[i], bb[j]);
    }
}

// ---- fp16 symmetric k-tile: BOTH operands from F [row][k] stride 40 ----
__device__ __forceinline__ void compute_tile_sym(uint32_t fAddr,
                                                 int lane, int wm, int wn, float acc[2][8][4]) {
#pragma unroll
    for (int ks = 0; ks < 2; ks++) {
        const int k0 = ks * 16;
        uint32_t a[2][4];
#pragma unroll
        for (int i = 0; i < 2; i++) {
            int row = wm + i * 16 + (lane & 15);
            int kof = k0 + ((lane >> 4) << 3);
            ldsm_x4(a[i], fAddr + row * (AH_STRIDE * 2) + kof * 2);
        }
        uint32_t bb[8][2];
#pragma unroll
        for (int j16 = 0; j16 < 4; j16++) {
            int mat = lane >> 3;
            int row = wn + j16 * 16 + (mat & 1) * 8 + (lane & 7);
            int kof = k0 + (mat >> 1) * 8;
            uint32_t rr[4];
            ldsm_x4(rr, fAddr + row * (AH_STRIDE * 2) + kof * 2);
            bb[j16 * 2][0] = rr[0]; bb[j16 * 2][1] = rr[2];
            bb[j16 * 2 + 1][0] = rr[1]; bb[j16 * 2 + 1][1] = rr[3];
        }
#pragma unroll
        for (int i = 0; i < 2; i++)
#pragma unroll
            for (int j = 0; j < 8; j++)
                mma_f16(acc[i][j], a[i], bb[j]);
    }
}

// ---- fp16 k-tile (K=32): A and B both [row][k] K-major, stride 136 halfs ----
#define WBS 136
__device__ __forceinline__ void compute_tile_ab136(uint32_t aAddr, uint32_t bAddr, int k0base,
                                                   int lane, int wm, int wn, float acc[2][8][4]) {
#pragma unroll
    for (int ks = 0; ks < 2; ks++) {
        const int k0 = k0base + ks * 16;
        uint32_t a[2][4];
#pragma unroll
        for (int i = 0; i < 2; i++) {
            int row = wm + i * 16 + (lane & 15);
            int kof = k0 + ((lane >> 4) << 3);
            ldsm_x4(a[i], aAddr + row * (WBS * 2) + kof * 2);
        }
        uint32_t bb[8][2];
#pragma unroll
        for (int j16 = 0; j16 < 4; j16++) {
            int mat = lane >> 3;
            int row = wn + j16 * 16 + (mat & 1) * 8 + (lane & 7);
            int kof = k0 + (mat >> 1) * 8;
            uint32_t rr[4];
            ldsm_x4(rr, bAddr + row * (WBS * 2) + kof * 2);
            bb[j16 * 2][0] = rr[0]; bb[j16 * 2][1] = rr[2];
            bb[j16 * 2 + 1][0] = rr[1]; bb[j16 * 2 + 1][1] = rr[3];
        }
#pragma unroll
        for (int i = 0; i < 2; i++)
#pragma unroll
            for (int j = 0; j < 8; j++)
                mma_f16(acc[i][j], a[i], bb[j]);
    }
}

// ---------------- prep ----------------
__global__ void k_prep(const float* __restrict__ w_o, const float* __restrict__ b_o,
                       const float* __restrict__ w_v, const float* __restrict__ b_v,
                       const float* __restrict__ w_c) {
    int i = blockIdx.x * blockDim.x + threadIdx.x;
    if (i < 128 * 256) {
        g_Wh[i] = __float2half(w_o[i]);
        g_Wh[128 * 256 + i] = __float2half(w_v[i]);
        g_Wch[i] = __float2half(w_c[i]);
    }
    if (i < 128) {
        g_bias[i] = b_o[i];
        g_bias[128 + i] = b_v[i];
    }
}

// ---------------- K1 fused: [o; F] where F = e^v * rsqrt(colsum e^v); partial row sums ----------------
#define K1_A_BUF (256 * AH_STRIDE)
#define K1_B_BUF (32 * BH_STRIDE)
#define K1_SMEM (2 * K1_A_BUF * 2 + 2 * K1_B_BUF * 2 + 4 * 128 * 4 + 2 * 128 * 4)
__global__ __launch_bounds__(512)
void k1_f16(const float* __restrict__ x) {
    extern __shared__ char smc[];
    __half* sAh = (__half*)smc;
    __half* sBw = (__half*)(smc + 2 * K1_A_BUF * 2);
    float* scs = (float*)(smc + 2 * K1_A_BUF * 2 + 2 * K1_B_BUF * 2);
    float* srs = scs + 4 * 128;
    const uint32_t ahA = smem_u32(sAh);
    const uint32_t bwA = smem_u32(sBw);

    const int t = threadIdx.x;
    const int lane = t & 31, wid = t >> 5;
    const int wm = (wid & 7) * 32, wn = (wid >> 3) * 64;
    const int b = blockIdx.y;
    const int col0 = blockIdx.x * 128;
    const float* Xb = x + (size_t)b * CIN * NPIX;

    float acc[2][8][4];
#pragma unroll
    for (int i = 0; i < 2; i++)
#pragma unroll
        for (int j = 0; j < 8; j++)
#pragma unroll
            for (int r = 0; r < 4; r++) acc[i][j][r] = 0.f;

    float4 xr[2];
#pragma unroll
    for (int i = 0; i < 2; i++) {
        int lin = t + i * 512;
        int r = lin >> 5, q = lin & 31;
        xr[i] = *(const float4*)(Xb + (size_t)r * NPIX + col0 + q * 4);
    }
#pragma unroll
    for (int i = 0; i < 2; i++) {
        int lin = t + i * 512;
        int r = lin >> 2, q = lin & 3;
        CP16(ahA + (uint32_t)(r * AH_STRIDE + q * 8) * 2, g_Wh + (size_t)r * 256 + q * 8);
    }
    CP_COMMIT;

    for (int kt = 0; kt < 8; kt++) {
        const int buf = kt & 1;
#pragma unroll
        for (int i = 0; i < 2; i++) {
            int lin = t + i * 512;
            int r = lin >> 5, q = lin & 31;
            __half2 h0 = __floats2half2_rn(xr[i].x, xr[i].y);
            __half2 h1 = __floats2half2_rn(xr[i].z, xr[i].w);
            uint2 pk = {*(uint32_t*)&h0, *(uint32_t*)&h1};
            *(uint2*)((char*)sBw + ((size_t)buf * K1_B_BUF + r * BH_STRIDE + q * 4) * 2) = pk;
        }
        if (kt < 7) {
            const int nbuf = (kt + 1) & 1;
            const int kc = (kt + 1) * 32;
#pragma unroll
            for (int i = 0; i < 2; i++) {
                int lin = t + i * 512;
                int r = lin >> 5, q = lin & 31;
                xr[i] = *(const float4*)(Xb + (size_t)(kc + r) * NPIX + col0 + q * 4);
            }
#pragma unroll
            for (int i = 0; i < 2; i++) {
                int lin = t + i * 512;
                int r = lin >> 2, q = lin & 3;
                CP16(ahA + (uint32_t)(nbuf * K1_A_BUF + r * AH_STRIDE + q * 8) * 2,
                     g_Wh + (size_t)r * 256 + kc + q * 8);
            }
            CP_COMMIT;
            CP_WAIT1;
        } else {
            CP_WAIT0;
        }
        __syncthreads();
        compute_tile_f16(ahA + buf * K1_A_BUF * 2, bwA + buf * K1_B_BUF * 2, lane, wm, wn, acc);
        __syncthreads();
    }

    const int lr = lane >> 2, lc = lane & 3;
    if (wm < 128) {
        __half* dst = g_oh + (size_t)b * 128 * NPIX;
#pragma unroll
        for (int i = 0; i < 2; i++) {
            int r1 = wm + i * 16 + lr, r2 = r1 + 8;
            float b1 = g_bias[r1], b2 = g_bias[r2];
#pragma unroll
            for (int j = 0; j < 8; j++) {
                int col = col0 + wn + j * 8 + lc * 2;
                __half2 h1 = __floats2half2_rn(acc[i][j][0] + b1, acc[i][j][1] + b1);
                __half2 h2 = __floats2half2_rn(acc[i][j][2] + b2, acc[i][j][3] + b2);
                *(__half2*)(dst + (size_t)r1 * NPIX + col) = h1;
                *(__half2*)(dst + (size_t)r2 * NPIX + col) = h2;
            }
        }
    } else {
        const int vb0 = wm - 128;
        float cs[16], rs[4];
#pragma unroll
        for (int c = 0; c < 16; c++) cs[c] = 0.f;
#pragma unroll
        for (int r = 0; r < 4; r++) rs[r] = 0.f;
#pragma unroll
        for (int i = 0; i < 2; i++) {
            int vr1 = vb0 + i * 16 + lr, vr2 = vr1 + 8;
            float b1 = g_bias[128 + vr1], b2 = g_bias[128 + vr2];
#pragma unroll
            for (int j = 0; j < 8; j++) {
                float e00 = __expf(acc[i][j][0] + b1);
                float e01 = __expf(acc[i][j][1] + b1);
                float e10 = __expf(acc[i][j][2] + b2);
                float e11 = __expf(acc[i][j][3] + b2);
                acc[i][j][0] = e00; acc[i][j][1] = e01;
                acc[i][j][2] = e10; acc[i][j][3] = e11;
                cs[j * 2]     += e00 + e10;
                cs[j * 2 + 1] += e01 + e11;
                rs[i * 2]     += e00 + e01;
                rs[i * 2 + 1] += e10 + e11;
            }
        }
#pragma unroll
        for (int c = 0; c < 16; c++) {
            cs[c] += __shfl_xor_sync(~0u, cs[c], 4);
            cs[c] += __shfl_xor_sync(~0u, cs[c], 8);
            cs[c] += __shfl_xor_sync(~0u, cs[c], 16);
        }
        if (lr == 0) {
            int vwi = (wid & 7) - 4;
#pragma unroll
            for (int j = 0; j < 8; j++) {
                scs[vwi * 128 + wn + j * 8 + lc * 2]     = cs[j * 2];
                scs[vwi * 128 + wn + j * 8 + lc * 2 + 1] = cs[j * 2 + 1];
            }
        }
#pragma unroll
        for (int r = 0; r < 4; r++) {
            rs[r] += __shfl_xor_sync(~0u, rs[r], 1);
            rs[r] += __shfl_xor_sync(~0u, rs[r], 2);
        }
        if (lc == 0) {
#pragma unroll
            for (int r = 0; r < 4; r++)
                srs[(wid >> 3) * 128 + vb0 + (r >> 1) * 16 + (r & 1) * 8 + lr] = rs[r];
        }
    }
    __syncthreads();
    if (t < 128) {
        float tot = scs[t] + scs[128 + t] + scs[256 + t] + scs[384 + t];
        scs[t] = rsqrtf(tot);
    } else if (t < 256) {
        int m = t - 128;
        g_rowpart[((size_t)b * MED + m) * 32 + blockIdx.x] = srs[m] + srs[128 + m];
    }
    __syncthreads();
    if (wm >= 128) {
        __half* dst = g_eh + (size_t)b * 128 * NPIX;
        const int vb0 = wm - 128;
#pragma unroll
        for (int i = 0; i < 2; i++) {
            int vr1 = vb0 + i * 16 + lr, vr2 = vr1 + 8;
#pragma unroll
            for (int j = 0; j < 8; j++) {
                int cl = wn + j * 8 + lc * 2;
                float s0 = scs[cl], s1 = scs[cl + 1];
                __half2 h1 = __floats2half2_rn(acc[i][j][0] * s0, acc[i][j][1] * s1);
                __half2 h2 = __floats2half2_rn(acc[i][j][2] * s0, acc[i][j][3] * s1);
                *(__half2*)(dst + (size_t)vr1 * NPIX + col0 + cl) = h1;
                *(__half2*)(dst + (size_t)vr2 * NPIX + col0 + cl) = h2;
            }
        }
    }
}

// ---------------- K4: S = F F^T, pure fp16 symmetric mma ----------------
#define K4_F_BUF (128 * AH_STRIDE)   // halfs
__global__ __launch_bounds__(256)
void k4_mma() {
    __shared__ __align__(16) __half F[2][K4_F_BUF];
    const uint32_t fA = smem_u32(F);

    const int t = threadIdx.x;
    const int lane = t & 31, wid = t >> 5;
    const int wm = (wid & 3) * 32, wn = (wid >> 2) * 64;
    const int split = blockIdx.x, b = blockIdx.y;
    const int n0 = split * 512;
    const __half* Eg = g_eh + (size_t)b * 128 * NPIX + n0;

    float acc[2][8][4];
#pragma unroll
    for (int i = 0; i < 2; i++)
#pragma unroll
        for (int j = 0; j < 8; j++)
#pragma unroll
            for (int r = 0; r < 4; r++) acc[i][j][r] = 0.f;

#pragma unroll
    for (int i = 0; i < 2; i++) {
        int lin = t + i * 256;
        int r = lin >> 2, qq = lin & 3;
        CP16(fA + (uint32_t)(r * AH_STRIDE + qq * 8) * 2, Eg + (size_t)r * NPIX + qq * 8);
    }
    CP_COMMIT;

    for (int s = 0; s < 16; s++) {
        const int buf = s & 1;
        if (s < 15) {
            const int nbuf = (s + 1) & 1;
            const int scol = (s + 1) * 32;
#pragma unroll
            for (int i = 0; i < 2; i++) {
                int lin = t + i * 256;
                int r = lin >> 2, qq = lin & 3;
                CP16(fA + (uint32_t)(nbuf * K4_F_BUF + r * AH_STRIDE + qq * 8) * 2,
                     Eg + (size_t)r * NPIX + scol + qq * 8);
            }
            CP_COMMIT;
            CP_WAIT1;
        } else {
            CP_WAIT0;
        }
        __syncthreads();
        compute_tile_sym(fA + buf * K4_F_BUF * 2, lane, wm, wn, acc);
        __syncthreads();
    }

    __half* out = g_Aph + ((size_t)b * 8 + split) * (MED * MED);
    const int lr = lane >> 2, lc = lane & 3;
#pragma unroll
    for (int i = 0; i < 2; i++) {
        int r1 = wm + i * 16 + lr, r2 = r1 + 8;
#pragma unroll
        for (int j = 0; j < 8; j++) {
            int col = wn + j * 8 + lc * 2;
            __half2 h1 = __floats2half2_rn(acc[i][j][0], acc[i][j][1]);
            __half2 h2 = __floats2half2_rn(acc[i][j][2], acc[i][j][3]);
            *(__half2*)(out + (size_t)r1 * MED + col) = h1;
            *(__half2*)(out + (size_t)r2 * MED + col) = h2;
        }
    }
}

// ---------------- gemmWb fused-reduce: Wbh[c][m] = alpha_m * sum_p (w_c . S_p^T) ----------------
// grid (BATCH, 2), block 256 (8 warps 4c x 2m). w_c resident; 8 partial tiles streamed.
#define WB_SMEM (128 * WBS * 2 + 2 * 128 * WBS * 2)   // A + 2x B = 104448 bytes
__global__ __launch_bounds__(256)
void k_gemmWb_f16() {
    extern __shared__ char smw[];
    __half* sA = (__half*)smw;                        // w_c [c][k] 128x136
    __half* sB = (__half*)(smw + 128 * WBS * 2);      // 2 x S_p [m][k] 128x136
    __shared__ float alpha_s[128];
    const uint32_t aA = smem_u32(sA);
    const uint32_t bA = smem_u32(sB);

    const int t = threadIdx.x;
    const int lane = t & 31, wid = t >> 5;
    const int wm = (wid & 3) * 32, wn = (wid >> 2) * 64;
    const int b = blockIdx.x, ch = blockIdx.y;
    const __half* Ag = g_Wch + (size_t)ch * 128 * 128;
    const __half* Pg = g_Aph + (size_t)b * 8 * (MED * MED);

    // prologue: A (w_c) + partial 0
#pragma unroll
    for (int i = 0; i < 8; i++) {
        int lin = t + i * 256;
        int r = lin >> 4, q = lin & 15;
        CP16(aA + (uint32_t)(r * WBS + q * 8) * 2, Ag + (size_t)r * 128 + q * 8);
        CP16(bA + (uint32_t)(r * WBS + q * 8) * 2, Pg + (size_t)r * 128 + q * 8);
    }
    CP_COMMIT;

    // alpha while loads fly
    if (t < 128) {
        const float* p = g_rowpart + ((size_t)b * MED + t) * 32;
        float s = 0.f;
#pragma unroll
        for (int i = 0; i < 32; i++) s += p[i];
        alpha_s[t] = 1.f / s;
    }

    float acc[2][8][4];
#pragma unroll
    for (int i = 0; i < 2; i++)
#pragma unroll
        for (int j = 0; j < 8; j++)
#pragma unroll
            for (int r = 0; r < 4; r++) acc[i][j][r] = 0.f;

    for (int p = 0; p < 8; p++) {
        const int buf = p & 1;
        if (p < 7) {
            const int nbuf = (p + 1) & 1;
            const __half* Pn = Pg + (size_t)(p + 1) * (MED * MED);
#pragma unroll
            for (int i = 0; i < 8; i++) {
                int lin = t + i * 256;
                int r = lin >> 4, q = lin & 15;
                CP16(bA + (uint32_t)(nbuf * 128 * WBS + r * WBS + q * 8) * 2,
                     Pn + (size_t)r * 128 + q * 8);
            }
            CP_COMMIT;
            CP_WAIT1;
        } else {
            CP_WAIT0;
        }
        __syncthreads();
#pragma unroll
        for (int kt = 0; kt < 4; kt++)
            compute_tile_ab136(aA, bA + (uint32_t)buf * 128 * WBS * 2, kt * 32,
                               lane, wm, wn, acc);
        __syncthreads();
    }

    __half* out = g_Wbh + (size_t)b * 256 * MED + (size_t)ch * 128 * MED;
    const int lr = lane >> 2, lc = lane & 3;
#pragma unroll
    for (int i = 0; i < 2; i++) {
        int c1 = wm + i * 16 + lr, c2 = c1 + 8;
#pragma unroll
        for (int j = 0; j < 8; j++) {
            int col = wn + j * 8 + lc * 2;
            float a0 = alpha_s[col], a1 = alpha_s[col + 1];
            __half2 h1 = __floats2half2_rn(acc[i][j][0] * a0, acc[i][j][1] * a1);
            __half2 h2 = __floats2half2_rn(acc[i][j][2] * a0, acc[i][j][3] * a1);
            *(__half2*)(out + (size_t)c1 * MED + col) = h1;
            *(__half2*)(out + (size_t)c2 * MED + col) = h2;
        }
    }
}

// ---------------- K6 merged: all 256 channels per pixel block ----------------
#define K6_A_BUF (256 * AH_STRIDE)
#define K6_B_BUF (32 * BH_STRIDE)
#define K6_SMEM (2 * K6_A_BUF * 2 + 2 * K6_B_BUF * 2)
__global__ __launch_bounds__(512)
void k6_f16(const float* __restrict__ x, const float* __restrict__ b_c,
            const float* __restrict__ gamma, float* __restrict__ outp) {
    extern __shared__ char smc6[];
    __half* sAh = (__half*)smc6;
    __half* sBw = (__half*)(smc6 + 2 * K6_A_BUF * 2);
    const uint32_t ahA = smem_u32(sAh);
    const uint32_t bwA = smem_u32(sBw);

    const int t = threadIdx.x;
    const int lane = t & 31, wid = t >> 5;
    const int wm = (wid & 7) * 32, wn = (wid >> 3) * 64;
    const int b = blockIdx.y;
    const int col0 = blockIdx.x * 128;
    const __half* Ab = g_Wbh + (size_t)b * 256 * MED;
    const __half* Ob = g_oh + (size_t)b * 128 * NPIX;

    float acc[2][8][4];
#pragma unroll
    for (int i = 0; i < 2; i++)
#pragma unroll
        for (int j = 0; j < 8; j++)
#pragma unroll
            for (int r = 0; r < 4; r++) acc[i][j][r] = 0.f;

    {
#pragma unroll
        for (int i = 0; i < 2; i++) {
            int lin = t + i * 512;
            int r = lin >> 2, q = lin & 3;
            CP16(ahA + (uint32_t)(r * AH_STRIDE + q * 8) * 2, Ab + (size_t)r * 128 + q * 8);
        }
        {
            int r = t >> 4, q = t & 15;
            CP16(bwA + (uint32_t)(r * BH_STRIDE + q * 8) * 2,
                 Ob + (size_t)r * NPIX + col0 + q * 8);
        }
        CP_COMMIT;
    }

    for (int kt = 0; kt < 4; kt++) {
        const int buf = kt & 1;
        if (kt < 3) {
            const int nbuf = (kt + 1) & 1;
            const int kc = (kt + 1) * 32;
#pragma unroll
            for (int i = 0; i < 2; i++) {
                int lin = t + i * 512;
                int r = lin >> 2, q = lin & 3;
                CP16(ahA + (uint32_t)(nbuf * K6_A_BUF + r * AH_STRIDE + q * 8) * 2,
                     Ab + (size_t)r * 128 + kc + q * 8);
            }
            {
                int r = t >> 4, q = t & 15;
                CP16(bwA + (uint32_t)(nbuf * K6_B_BUF + r * BH_STRIDE + q * 8) * 2,
                     Ob + (size_t)(kc + r) * NPIX + col0 + q * 8);
            }
            CP_COMMIT;
            CP_WAIT1;
        } else {
            CP_WAIT0;
        }
        __syncthreads();
        compute_tile_f16(ahA + buf * K6_A_BUF * 2, bwA + buf * K6_B_BUF * 2, lane, wm, wn, acc);
        __syncthreads();
    }

    const float g = gamma[0];
    const int lr = lane >> 2, lc = lane & 3;
#pragma unroll
    for (int i = 0; i < 2; i++) {
        int c1 = wm + i * 16 + lr;
        int c2 = c1 + 8;
        float bc1 = b_c[c1], bc2 = b_c[c2];
#pragma unroll
        for (int j = 0; j < 8; j++) {
            int col = col0 + wn + j * 8 + lc * 2;
            float2 xv1 = *(const float2*)(x + ((size_t)b * CIN + c1) * NPIX + col);
            float2 xv2 = *(const float2*)(x + ((size_t)b * CIN + c2) * NPIX + col);
            float2 o1, o2;
            o1.x = fmaxf(acc[i][j][0] + bc1, 0.f) * g + xv1.x;
            o1.y = fmaxf(acc[i][j][1] + bc1, 0.f) * g + xv1.y;
            o2.x = fmaxf(acc[i][j][2] + bc2, 0.f) * g + xv2.x;
            o2.y = fmaxf(acc[i][j][3] + bc2, 0.f) * g + xv2.y;
            *(float2*)(outp + ((size_t)b * CIN + c1) * NPIX + col) = o1;
            *(float2*)(outp + ((size_t)b * CIN + c2) * NPIX + col) = o2;
        }
    }
}

// ---------------- launch ----------------
extern "C" void kernel_launch(void* const* d_in, const int* in_sizes, int n_in,
                              void* d_out, int out_size) {
    const float* x     = (const float*)d_in[0];
    const float* w_o   = (const float*)d_in[1];
    const float* b_o   = (const float*)d_in[2];
    const float* w_v   = (const float*)d_in[3];
    const float* b_v   = (const float*)d_in[4];
    const float* w_c   = (const float*)d_in[5];
    const float* b_c   = (const float*)d_in[6];
    const float* gamma = (const float*)d_in[7];
    float* out = (float*)d_out;

    cudaFuncSetAttribute(k1_f16, cudaFuncAttributeMaxDynamicSharedMemorySize, K1_SMEM);
    cudaFuncSetAttribute(k6_f16, cudaFuncAttributeMaxDynamicSharedMemorySize, K6_SMEM);
    cudaFuncSetAttribute(k_gemmWb_f16, cudaFuncAttributeMaxDynamicSharedMemorySize, WB_SMEM);

    k_prep<<<128, 256>>>(w_o, b_o, w_v, b_v, w_c);
    k1_f16<<<dim3(32, BATCH), 512, K1_SMEM>>>(x);
    k4_mma<<<dim3(8, BATCH), 256>>>();
    k_gemmWb_f16<<<dim3(BATCH, 2), 256, WB_SMEM>>>();
    k6_f16<<<dim3(32, BATCH), 512, K6_SMEM>>>(x, b_c, gamma, out);
}

// round 13
// speedup vs baseline: 1.1843x; 1.1843x over previous
#include <cuda_runtime.h>
#include <cuda_fp16.h>
#include <cstdint>

#define BATCH 16
#define CIN   256
#define MED   128
#define NPIX  4096

// ---------------- scratch ----------------
__device__ __half g_Wh[256 * 256];                    // stacked [w_o; w_v] half
__device__ __half g_Wch[256 * 128];                   // w_c half [c][k]
__device__ float  g_bias[256];
__device__ __half g_oh[(size_t)BATCH * 128 * NPIX];   // o half
__device__ __half g_eh[(size_t)BATCH * 128 * NPIX];   // F = e^v * rsqrt(colsum) half
__device__ float  g_rowpart[BATCH * MED * 32];        // partial row sums of e^v
__device__ __half g_Aph[(size_t)BATCH * 8 * MED * MED]; // split-K partials of S (half)
__device__ __half g_Ah[BATCH * MED * MED];            // alpha-scaled S, half [m][k]
__device__ __half g_Wbh[BATCH * 256 * MED];           // Wb half [b][c][m]

// ======================= helpers =======================
__device__ __forceinline__ uint32_t smem_u32(const void* p) {
    uint32_t a;
    asm("{ .reg .u64 t; cvta.to.shared.u64 t, %1; cvt.u32.u64 %0, t; }" : "=r"(a) : "l"(p));
    return a;
}

#define CP16(dst, src) \
    asm volatile("cp.async.ca.shared.global [%0], [%1], 16;" :: "r"(dst), "l"(src) : "memory")
#define CP_COMMIT asm volatile("cp.async.commit_group;" ::: "memory")
#define CP_WAIT1  asm volatile("cp.async.wait_group 1;" ::: "memory")
#define CP_WAIT0  asm volatile("cp.async.wait_group 0;" ::: "memory")

__device__ __forceinline__ void mma_f16(float* d, const uint32_t* a, const uint32_t* b) {
    asm volatile(
        "mma.sync.aligned.m16n8k16.row.col.f32.f16.f16.f32 "
        "{%0,%1,%2,%3}, {%4,%5,%6,%7}, {%8,%9}, {%0,%1,%2,%3};"
        : "+f"(d[0]), "+f"(d[1]), "+f"(d[2]), "+f"(d[3])
        : "r"(a[0]), "r"(a[1]), "r"(a[2]), "r"(a[3]), "r"(b[0]), "r"(b[1]));
}

__device__ __forceinline__ void ldsm_x4(uint32_t* r, uint32_t a) {
    asm volatile("ldmatrix.sync.aligned.m8n8.x4.shared.b16 {%0,%1,%2,%3}, [%4];"
                 : "=r"(r[0]), "=r"(r[1]), "=r"(r[2]), "=r"(r[3]) : "r"(a));
}
__device__ __forceinline__ void ldsm_x4_t(uint32_t* r, uint32_t a) {
    asm volatile("ldmatrix.sync.aligned.m8n8.x4.trans.shared.b16 {%0,%1,%2,%3}, [%4];"
                 : "=r"(r[0]), "=r"(r[1]), "=r"(r[2]), "=r"(r[3]) : "r"(a));
}

#define AH_STRIDE 40    // halfs; 80B rows
#define BH_STRIDE 136   // halfs; 272B rows

// ---- fp16 k-tile (K=32): A [m][k] stride 40, B raw [k][n] stride 136 ----
__device__ __forceinline__ void compute_tile_f16(uint32_t ahAddr, uint32_t bwAddr,
                                                 int lane, int wm, int wn, float acc[2][8][4]) {
#pragma unroll
    for (int ks = 0; ks < 2; ks++) {
        const int k0 = ks * 16;
        uint32_t a[2][4];
#pragma unroll
        for (int i = 0; i < 2; i++) {
            int row = wm + i * 16 + (lane & 15);
            int kof = k0 + ((lane >> 4) << 3);
            ldsm_x4(a[i], ahAddr + row * (AH_STRIDE * 2) + kof * 2);
        }
        uint32_t bb[8][2];
#pragma unroll
        for (int j16 = 0; j16 < 4; j16++) {
            int krow = k0 + (lane & 7) + ((lane & 8) ? 8 : 0);
            int ncol = wn + j16 * 16 + ((lane & 16) ? 8 : 0);
            uint32_t rr[4];
            ldsm_x4_t(rr, bwAddr + krow * (BH_STRIDE * 2) + ncol * 2);
            bb[j16 * 2][0] = rr[0]; bb[j16 * 2][1] = rr[1];
            bb[j16 * 2 + 1][0] = rr[2]; bb[j16 * 2 + 1][1] = rr[3];
        }
#pragma unroll
        for (int i = 0; i < 2; i++)
#pragma unroll
            for (int j = 0; j < 8; j++)
                mma_f16(acc[i][j], a[i], bb[j]);
    }
}

// ---- fp16 symmetric k-tile: BOTH operands from F [row][k] stride 40 ----
__device__ __forceinline__ void compute_tile_sym(uint32_t fAddr,
                                                 int lane, int wm, int wn, float acc[2][8][4]) {
#pragma unroll
    for (int ks = 0; ks < 2; ks++) {
        const int k0 = ks * 16;
        uint32_t a[2][4];
#pragma unroll
        for (int i = 0; i < 2; i++) {
            int row = wm + i * 16 + (lane & 15);
            int kof = k0 + ((lane >> 4) << 3);
            ldsm_x4(a[i], fAddr + row * (AH_STRIDE * 2) + kof * 2);
        }
        uint32_t bb[8][2];
#pragma unroll
        for (int j16 = 0; j16 < 4; j16++) {
            int mat = lane >> 3;
            int row = wn + j16 * 16 + (mat & 1) * 8 + (lane & 7);
            int kof = k0 + (mat >> 1) * 8;
            uint32_t rr[4];
            ldsm_x4(rr, fAddr + row * (AH_STRIDE * 2) + kof * 2);
            bb[j16 * 2][0] = rr[0]; bb[j16 * 2][1] = rr[2];
            bb[j16 * 2 + 1][0] = rr[1]; bb[j16 * 2 + 1][1] = rr[3];
        }
#pragma unroll
        for (int i = 0; i < 2; i++)
#pragma unroll
            for (int j = 0; j < 8; j++)
                mma_f16(acc[i][j], a[i], bb[j]);
    }
}

// ---- fp16 k-tile (K=32): A and B both [row][k] K-major, stride 136 halfs ----
#define WBS 136
__device__ __forceinline__ void compute_tile_ab136(uint32_t aAddr, uint32_t bAddr, int k0base,
                                                   int lane, int wm, int wn, float acc[2][8][4]) {
#pragma unroll
    for (int ks = 0; ks < 2; ks++) {
        const int k0 = k0base + ks * 16;
        uint32_t a[2][4];
#pragma unroll
        for (int i = 0; i < 2; i++) {
            int row = wm + i * 16 + (lane & 15);
            int kof = k0 + ((lane >> 4) << 3);
            ldsm_x4(a[i], aAddr + row * (WBS * 2) + kof * 2);
        }
        uint32_t bb[8][2];
#pragma unroll
        for (int j16 = 0; j16 < 4; j16++) {
            int mat = lane >> 3;
            int row = wn + j16 * 16 + (mat & 1) * 8 + (lane & 7);
            int kof = k0 + (mat >> 1) * 8;
            uint32_t rr[4];
            ldsm_x4(rr, bAddr + row * (WBS * 2) + kof * 2);
            bb[j16 * 2][0] = rr[0]; bb[j16 * 2][1] = rr[2];
            bb[j16 * 2 + 1][0] = rr[1]; bb[j16 * 2 + 1][1] = rr[3];
        }
#pragma unroll
        for (int i = 0; i < 2; i++)
#pragma unroll
            for (int j = 0; j < 8; j++)
                mma_f16(acc[i][j], a[i], bb[j]);
    }
}

// ---------------- prep ----------------
__global__ void k_prep(const float* __restrict__ w_o, const float* __restrict__ b_o,
                       const float* __restrict__ w_v, const float* __restrict__ b_v,
                       const float* __restrict__ w_c) {
    int i = blockIdx.x * blockDim.x + threadIdx.x;
    if (i < 128 * 256) {
        g_Wh[i] = __float2half(w_o[i]);
        g_Wh[128 * 256 + i] = __float2half(w_v[i]);
        g_Wch[i] = __float2half(w_c[i]);
    }
    if (i < 128) {
        g_bias[i] = b_o[i];
        g_bias[128 + i] = b_v[i];
    }
}

// ---------------- K1 fused: [o; F] where F = e^v * rsqrt(colsum e^v); partial row sums ----------------
#define K1_A_BUF (256 * AH_STRIDE)
#define K1_B_BUF (32 * BH_STRIDE)
#define K1_SMEM (2 * K1_A_BUF * 2 + 2 * K1_B_BUF * 2 + 4 * 128 * 4 + 2 * 128 * 4)
__global__ __launch_bounds__(512)
void k1_f16(const float* __restrict__ x) {
    extern __shared__ char smc[];
    __half* sAh = (__half*)smc;
    __half* sBw = (__half*)(smc + 2 * K1_A_BUF * 2);
    float* scs = (float*)(smc + 2 * K1_A_BUF * 2 + 2 * K1_B_BUF * 2);
    float* srs = scs + 4 * 128;
    const uint32_t ahA = smem_u32(sAh);
    const uint32_t bwA = smem_u32(sBw);

    const int t = threadIdx.x;
    const int lane = t & 31, wid = t >> 5;
    const int wm = (wid & 7) * 32, wn = (wid >> 3) * 64;
    const int b = blockIdx.y;
    const int col0 = blockIdx.x * 128;
    const float* Xb = x + (size_t)b * CIN * NPIX;

    float acc[2][8][4];
#pragma unroll
    for (int i = 0; i < 2; i++)
#pragma unroll
        for (int j = 0; j < 8; j++)
#pragma unroll
            for (int r = 0; r < 4; r++) acc[i][j][r] = 0.f;

    float4 xr[2];
#pragma unroll
    for (int i = 0; i < 2; i++) {
        int lin = t + i * 512;
        int r = lin >> 5, q = lin & 31;
        xr[i] = *(const float4*)(Xb + (size_t)r * NPIX + col0 + q * 4);
    }
#pragma unroll
    for (int i = 0; i < 2; i++) {
        int lin = t + i * 512;
        int r = lin >> 2, q = lin & 3;
        CP16(ahA + (uint32_t)(r * AH_STRIDE + q * 8) * 2, g_Wh + (size_t)r * 256 + q * 8);
    }
    CP_COMMIT;

    for (int kt = 0; kt < 8; kt++) {
        const int buf = kt & 1;
#pragma unroll
        for (int i = 0; i < 2; i++) {
            int lin = t + i * 512;
            int r = lin >> 5, q = lin & 31;
            __half2 h0 = __floats2half2_rn(xr[i].x, xr[i].y);
            __half2 h1 = __floats2half2_rn(xr[i].z, xr[i].w);
            uint2 pk = {*(uint32_t*)&h0, *(uint32_t*)&h1};
            *(uint2*)((char*)sBw + ((size_t)buf * K1_B_BUF + r * BH_STRIDE + q * 4) * 2) = pk;
        }
        if (kt < 7) {
            const int nbuf = (kt + 1) & 1;
            const int kc = (kt + 1) * 32;
#pragma unroll
            for (int i = 0; i < 2; i++) {
                int lin = t + i * 512;
                int r = lin >> 5, q = lin & 31;
                xr[i] = *(const float4*)(Xb + (size_t)(kc + r) * NPIX + col0 + q * 4);
            }
#pragma unroll
            for (int i = 0; i < 2; i++) {
                int lin = t + i * 512;
                int r = lin >> 2, q = lin & 3;
                CP16(ahA + (uint32_t)(nbuf * K1_A_BUF + r * AH_STRIDE + q * 8) * 2,
                     g_Wh + (size_t)r * 256 + kc + q * 8);
            }
            CP_COMMIT;
            CP_WAIT1;
        } else {
            CP_WAIT0;
        }
        __syncthreads();
        compute_tile_f16(ahA + buf * K1_A_BUF * 2, bwA + buf * K1_B_BUF * 2, lane, wm, wn, acc);
        // no trailing barrier: next iter touches only the other buffer, whose
        // last readers all passed the pre-compute barrier above.
    }

    __syncthreads();   // all compute done before sums/epilogue use smem
    const int lr = lane >> 2, lc = lane & 3;
    if (wm < 128) {
        __half* dst = g_oh + (size_t)b * 128 * NPIX;
#pragma unroll
        for (int i = 0; i < 2; i++) {
            int r1 = wm + i * 16 + lr, r2 = r1 + 8;
            float b1 = g_bias[r1], b2 = g_bias[r2];
#pragma unroll
            for (int j = 0; j < 8; j++) {
                int col = col0 + wn + j * 8 + lc * 2;
                __half2 h1 = __floats2half2_rn(acc[i][j][0] + b1, acc[i][j][1] + b1);
                __half2 h2 = __floats2half2_rn(acc[i][j][2] + b2, acc[i][j][3] + b2);
                *(__half2*)(dst + (size_t)r1 * NPIX + col) = h1;
                *(__half2*)(dst + (size_t)r2 * NPIX + col) = h2;
            }
        }
    } else {
        const int vb0 = wm - 128;
        float cs[16], rs[4];
#pragma unroll
        for (int c = 0; c < 16; c++) cs[c] = 0.f;
#pragma unroll
        for (int r = 0; r < 4; r++) rs[r] = 0.f;
#pragma unroll
        for (int i = 0; i < 2; i++) {
            int vr1 = vb0 + i * 16 + lr, vr2 = vr1 + 8;
            float b1 = g_bias[128 + vr1], b2 = g_bias[128 + vr2];
#pragma unroll
            for (int j = 0; j < 8; j++) {
                float e00 = __expf(acc[i][j][0] + b1);
                float e01 = __expf(acc[i][j][1] + b1);
                float e10 = __expf(acc[i][j][2] + b2);
                float e11 = __expf(acc[i][j][3] + b2);
                acc[i][j][0] = e00; acc[i][j][1] = e01;
                acc[i][j][2] = e10; acc[i][j][3] = e11;
                cs[j * 2]     += e00 + e10;
                cs[j * 2 + 1] += e01 + e11;
                rs[i * 2]     += e00 + e01;
                rs[i * 2 + 1] += e10 + e11;
            }
        }
#pragma unroll
        for (int c = 0; c < 16; c++) {
            cs[c] += __shfl_xor_sync(~0u, cs[c], 4);
            cs[c] += __shfl_xor_sync(~0u, cs[c], 8);
            cs[c] += __shfl_xor_sync(~0u, cs[c], 16);
        }
        if (lr == 0) {
            int vwi = (wid & 7) - 4;
#pragma unroll
            for (int j = 0; j < 8; j++) {
                scs[vwi * 128 + wn + j * 8 + lc * 2]     = cs[j * 2];
                scs[vwi * 128 + wn + j * 8 + lc * 2 + 1] = cs[j * 2 + 1];
            }
        }
#pragma unroll
        for (int r = 0; r < 4; r++) {
            rs[r] += __shfl_xor_sync(~0u, rs[r], 1);
            rs[r] += __shfl_xor_sync(~0u, rs[r], 2);
        }
        if (lc == 0) {
#pragma unroll
            for (int r = 0; r < 4; r++)
                srs[(wid >> 3) * 128 + vb0 + (r >> 1) * 16 + (r & 1) * 8 + lr] = rs[r];
        }
    }
    __syncthreads();
    if (t < 128) {
        float tot = scs[t] + scs[128 + t] + scs[256 + t] + scs[384 + t];
        scs[t] = rsqrtf(tot);
    } else if (t < 256) {
        int m = t - 128;
        g_rowpart[((size_t)b * MED + m) * 32 + blockIdx.x] = srs[m] + srs[128 + m];
    }
    __syncthreads();
    if (wm >= 128) {
        __half* dst = g_eh + (size_t)b * 128 * NPIX;
        const int vb0 = wm - 128;
#pragma unroll
        for (int i = 0; i < 2; i++) {
            int vr1 = vb0 + i * 16 + lr, vr2 = vr1 + 8;
#pragma unroll
            for (int j = 0; j < 8; j++) {
                int cl = wn + j * 8 + lc * 2;
                float s0 = scs[cl], s1 = scs[cl + 1];
                __half2 h1 = __floats2half2_rn(acc[i][j][0] * s0, acc[i][j][1] * s1);
                __half2 h2 = __floats2half2_rn(acc[i][j][2] * s0, acc[i][j][3] * s1);
                *(__half2*)(dst + (size_t)vr1 * NPIX + col0 + cl) = h1;
                *(__half2*)(dst + (size_t)vr2 * NPIX + col0 + cl) = h2;
            }
        }
    }
}

// ---------------- K4: S = F F^T, pure fp16 symmetric mma ----------------
#define K4_F_BUF (128 * AH_STRIDE)   // halfs
__global__ __launch_bounds__(256)
void k4_mma() {
    __shared__ __align__(16) __half F[2][K4_F_BUF];
    const uint32_t fA = smem_u32(F);

    const int t = threadIdx.x;
    const int lane = t & 31, wid = t >> 5;
    const int wm = (wid & 3) * 32, wn = (wid >> 2) * 64;
    const int split = blockIdx.x, b = blockIdx.y;
    const int n0 = split * 512;
    const __half* Eg = g_eh + (size_t)b * 128 * NPIX + n0;

    float acc[2][8][4];
#pragma unroll
    for (int i = 0; i < 2; i++)
#pragma unroll
        for (int j = 0; j < 8; j++)
#pragma unroll
            for (int r = 0; r < 4; r++) acc[i][j][r] = 0.f;

#pragma unroll
    for (int i = 0; i < 2; i++) {
        int lin = t + i * 256;
        int r = lin >> 2, qq = lin & 3;
        CP16(fA + (uint32_t)(r * AH_STRIDE + qq * 8) * 2, Eg + (size_t)r * NPIX + qq * 8);
    }
    CP_COMMIT;

    for (int s = 0; s < 16; s++) {
        const int buf = s & 1;
        if (s < 15) {
            const int nbuf = (s + 1) & 1;
            const int scol = (s + 1) * 32;
#pragma unroll
            for (int i = 0; i < 2; i++) {
                int lin = t + i * 256;
                int r = lin >> 2, qq = lin & 3;
                CP16(fA + (uint32_t)(nbuf * K4_F_BUF + r * AH_STRIDE + qq * 8) * 2,
                     Eg + (size_t)r * NPIX + scol + qq * 8);
            }
            CP_COMMIT;
            CP_WAIT1;
        } else {
            CP_WAIT0;
        }
        __syncthreads();
        compute_tile_sym(fA + buf * K4_F_BUF * 2, lane, wm, wn, acc);
        // no trailing barrier (double-buffer, 1-barrier scheme)
    }

    __half* out = g_Aph + ((size_t)b * 8 + split) * (MED * MED);
    const int lr = lane >> 2, lc = lane & 3;
#pragma unroll
    for (int i = 0; i < 2; i++) {
        int r1 = wm + i * 16 + lr, r2 = r1 + 8;
#pragma unroll
        for (int j = 0; j < 8; j++) {
            int col = wn + j * 8 + lc * 2;
            __half2 h1 = __floats2half2_rn(acc[i][j][0], acc[i][j][1]);
            __half2 h2 = __floats2half2_rn(acc[i][j][2], acc[i][j][3]);
            *(__half2*)(out + (size_t)r1 * MED + col) = h1;
            *(__half2*)(out + (size_t)r2 * MED + col) = h2;
        }
    }
}

// ---------------- reduceA: A'h[m][k] = half(alpha_m * sum_p partials) ----------------
// grid (32, BATCH), block 256; each block: 4 m-rows x 128 k, 2 elems/thread
__global__ __launch_bounds__(256)
void k_reduceA() {
    __shared__ float alpha_s[4];
    const int b = blockIdx.y, mblk = blockIdx.x;
    const int t = threadIdx.x;
    if (t < 4) {
        const float* p = g_rowpart + ((size_t)b * MED + mblk * 4 + t) * 32;
        float s = 0.f;
#pragma unroll
        for (int i = 0; i < 32; i++) s += p[i];
        alpha_s[t] = 1.f / s;
    }
    __syncthreads();

    const int e0 = t * 2;
    const int ml = e0 >> 7, k = e0 & 127;
    const __half* base = g_Aph + (size_t)b * 8 * (MED * MED) + (size_t)(mblk * 4 + ml) * 128 + k;
    float sx = 0.f, sy = 0.f;
#pragma unroll
    for (int p = 0; p < 8; p++) {
        float2 a = __half22float2(*(const __half2*)(base + (size_t)p * (MED * MED)));
        sx += a.x; sy += a.y;
    }
    const float al = alpha_s[ml];
    __half2 h = __floats2half2_rn(sx * al, sy * al);
    *(__half2*)(g_Ah + (size_t)b * (MED * MED) + (size_t)(mblk * 4 + ml) * 128 + k) = h;
}

// ---------------- gemmWb fp16: Wbh[c][m] = w_c[c][:] . A'[m][:] ----------------
#define WB_SMEM (2 * 128 * WBS * 2)
__global__ __launch_bounds__(256)
void k_gemmWb_f16() {
    extern __shared__ char smw[];
    __half* sA = (__half*)smw;
    __half* sB = (__half*)(smw + 128 * WBS * 2);
    const uint32_t aA = smem_u32(sA);
    const uint32_t bA = smem_u32(sB);

    const int t = threadIdx.x;
    const int lane = t & 31, wid = t >> 5;
    const int wm = (wid & 3) * 32, wn = (wid >> 2) * 64;
    const int b = blockIdx.x, ch = blockIdx.y;
    const __half* Ag = g_Wch + (size_t)ch * 128 * 128;
    const __half* Bg = g_Ah + (size_t)b * (MED * MED);

#pragma unroll
    for (int i = 0; i < 8; i++) {
        int lin = t + i * 256;
        int r = lin >> 4, q = lin & 15;
        CP16(aA + (uint32_t)(r * WBS + q * 8) * 2, Ag + (size_t)r * 128 + q * 8);
        CP16(bA + (uint32_t)(r * WBS + q * 8) * 2, Bg + (size_t)r * 128 + q * 8);
    }
    CP_COMMIT;

    float acc[2][8][4];
#pragma unroll
    for (int i = 0; i < 2; i++)
#pragma unroll
        for (int j = 0; j < 8; j++)
#pragma unroll
            for (int r = 0; r < 4; r++) acc[i][j][r] = 0.f;

    CP_WAIT0;
    __syncthreads();
#pragma unroll
    for (int kt = 0; kt < 4; kt++)
        compute_tile_ab136(aA, bA, kt * 32, lane, wm, wn, acc);

    __half* out = g_Wbh + (size_t)b * 256 * MED + (size_t)ch * 128 * MED;
    const int lr = lane >> 2, lc = lane & 3;
#pragma unroll
    for (int i = 0; i < 2; i++) {
        int c1 = wm + i * 16 + lr, c2 = c1 + 8;
#pragma unroll
        for (int j = 0; j < 8; j++) {
            int col = wn + j * 8 + lc * 2;
            __half2 h1 = __floats2half2_rn(acc[i][j][0], acc[i][j][1]);
            __half2 h2 = __floats2half2_rn(acc[i][j][2], acc[i][j][3]);
            *(__half2*)(out + (size_t)c1 * MED + col) = h1;
            *(__half2*)(out + (size_t)c2 * MED + col) = h2;
        }
    }
}

// ---------------- K6 merged: all 256 channels per pixel block ----------------
#define K6_A_BUF (256 * AH_STRIDE)
#define K6_B_BUF (32 * BH_STRIDE)
#define K6_SMEM (2 * K6_A_BUF * 2 + 2 * K6_B_BUF * 2)
__global__ __launch_bounds__(512)
void k6_f16(const float* __restrict__ x, const float* __restrict__ b_c,
            const float* __restrict__ gamma, float* __restrict__ outp) {
    extern __shared__ char smc6[];
    __half* sAh = (__half*)smc6;
    __half* sBw = (__half*)(smc6 + 2 * K6_A_BUF * 2);
    const uint32_t ahA = smem_u32(sAh);
    const uint32_t bwA = smem_u32(sBw);

    const int t = threadIdx.x;
    const int lane = t & 31, wid = t >> 5;
    const int wm = (wid & 7) * 32, wn = (wid >> 3) * 64;
    const int b = blockIdx.y;
    const int col0 = blockIdx.x * 128;
    const __half* Ab = g_Wbh + (size_t)b * 256 * MED;
    const __half* Ob = g_oh + (size_t)b * 128 * NPIX;

    float acc[2][8][4];
#pragma unroll
    for (int i = 0; i < 2; i++)
#pragma unroll
        for (int j = 0; j < 8; j++)
#pragma unroll
            for (int r = 0; r < 4; r++) acc[i][j][r] = 0.f;

    {
#pragma unroll
        for (int i = 0; i < 2; i++) {
            int lin = t + i * 512;
            int r = lin >> 2, q = lin & 3;
            CP16(ahA + (uint32_t)(r * AH_STRIDE + q * 8) * 2, Ab + (size_t)r * 128 + q * 8);
        }
        {
            int r = t >> 4, q = t & 15;
            CP16(bwA + (uint32_t)(r * BH_STRIDE + q * 8) * 2,
                 Ob + (size_t)r * NPIX + col0 + q * 8);
        }
        CP_COMMIT;
    }

    for (int kt = 0; kt < 4; kt++) {
        const int buf = kt & 1;
        if (kt < 3) {
            const int nbuf = (kt + 1) & 1;
            const int kc = (kt + 1) * 32;
#pragma unroll
            for (int i = 0; i < 2; i++) {
                int lin = t + i * 512;
                int r = lin >> 2, q = lin & 3;
                CP16(ahA + (uint32_t)(nbuf * K6_A_BUF + r * AH_STRIDE + q * 8) * 2,
                     Ab + (size_t)r * 128 + kc + q * 8);
            }
            {
                int r = t >> 4, q = t & 15;
                CP16(bwA + (uint32_t)(nbuf * K6_B_BUF + r * BH_STRIDE + q * 8) * 2,
                     Ob + (size_t)(kc + r) * NPIX + col0 + q * 8);
            }
            CP_COMMIT;
            CP_WAIT1;
        } else {
            CP_WAIT0;
        }
        __syncthreads();
        compute_tile_f16(ahA + buf * K6_A_BUF * 2, bwA + buf * K6_B_BUF * 2, lane, wm, wn, acc);
        // no trailing barrier
    }

    const float g = gamma[0];
    const int lr = lane >> 2, lc = lane & 3;
#pragma unroll
    for (int i = 0; i < 2; i++) {
        int c1 = wm + i * 16 + lr;
        int c2 = c1 + 8;
        float bc1 = b_c[c1], bc2 = b_c[c2];
#pragma unroll
        for (int j = 0; j < 8; j++) {
            int col = col0 + wn + j * 8 + lc * 2;
            float2 xv1 = *(const float2*)(x + ((size_t)b * CIN + c1) * NPIX + col);
            float2 xv2 = *(const float2*)(x + ((size_t)b * CIN + c2) * NPIX + col);
            float2 o1, o2;
            o1.x = fmaxf(acc[i][j][0] + bc1, 0.f) * g + xv1.x;
            o1.y = fmaxf(acc[i][j][1] + bc1, 0.f) * g + xv1.y;
            o2.x = fmaxf(acc[i][j][2] + bc2, 0.f) * g + xv2.x;
            o2.y = fmaxf(acc[i][j][3] + bc2, 0.f) * g + xv2.y;
            *(float2*)(outp + ((size_t)b * CIN + c1) * NPIX + col) = o1;
            *(float2*)(outp + ((size_t)b * CIN + c2) * NPIX + col) = o2;
        }
    }
}

// ---------------- launch ----------------
extern "C" void kernel_launch(void* const* d_in, const int* in_sizes, int n_in,
                              void* d_out, int out_size) {
    const float* x     = (const float*)d_in[0];
    const float* w_o   = (const float*)d_in[1];
    const float* b_o   = (const float*)d_in[2];
    const float* w_v   = (const float*)d_in[3];
    const float* b_v   = (const float*)d_in[4];
    const float* w_c   = (const float*)d_in[5];
    const float* b_c   = (const float*)d_in[6];
    const float* gamma = (const float*)d_in[7];
    float* out = (float*)d_out;

    cudaFuncSetAttribute(k1_f16, cudaFuncAttributeMaxDynamicSharedMemorySize, K1_SMEM);
    cudaFuncSetAttribute(k6_f16, cudaFuncAttributeMaxDynamicSharedMemorySize, K6_SMEM);
    cudaFuncSetAttribute(k_gemmWb_f16, cudaFuncAttributeMaxDynamicSharedMemorySize, WB_SMEM);

    k_prep<<<128, 256>>>(w_o, b_o, w_v, b_v, w_c);
    k1_f16<<<dim3(32, BATCH), 512, K1_SMEM>>>(x);
    k4_mma<<<dim3(8, BATCH), 256>>>();
    k_reduceA<<<dim3(32, BATCH), 256>>>();
    k_gemmWb_f16<<<dim3(BATCH, 2), 256, WB_SMEM>>>();
    k6_f16<<<dim3(32, BATCH), 512, K6_SMEM>>>(x, b_c, gamma, out);
}